// round 9
// baseline (speedup 1.0000x reference)
#include <cuda_runtime.h>
#include <math.h>

#define T_STEPS 500
#define BATCH   128
#define FDIM    128
#define HDIM    512
#define ODIM    32

#define NG  16     // batch groups
#define GSZ 8      // batches per group
#define NS  8      // H slices (CTAs per group)
#define DSTW 64    // dst neurons per slice

#define GBM 128
#define GBN 128
#define GBK 32

// Device-global scratch (sanctioned allocation-free path)
__device__ float g_iin[T_STEPS * BATCH * HDIM];          // x @ W_in^T
__device__ float g_wrecT[HDIM * HDIM];                   // W_rec^T [src][dst]
__device__ float g_woutT[HDIM * ODIM];                   // W_out^T [h][o]
__device__ unsigned long long g_zall[T_STEPS * NG * GSZ * NS];  // spike masks
__device__ int   g_flag[T_STEPS * NG * NS];              // per-(t,g,s) publish flag

// ---------------------------------------------------------------------------
// Transposes + zero per-replay publish flags
// ---------------------------------------------------------------------------
__global__ void transpose_kernel(const float* __restrict__ W_rec,
                                 const float* __restrict__ W_out) {
    int idx = blockIdx.x * blockDim.x + threadIdx.x;
    if (idx < HDIM * HDIM) {
        int r = idx / HDIM, c = idx % HDIM;
        g_wrecT[c * HDIM + r] = W_rec[idx];
    }
    if (idx < ODIM * HDIM) {
        int o = idx / HDIM, h = idx % HDIM;
        g_woutT[h * ODIM + o] = W_out[idx];
    }
    if (idx < T_STEPS * NG * NS) g_flag[idx] = 0;
}

// ---------------------------------------------------------------------------
// GEMM: g_iin[m,n] = sum_k X[m,k] * W_in[n,k]   (verbatim — verified)
// ---------------------------------------------------------------------------
__global__ void __launch_bounds__(256) gemm_iin_kernel(
    const float* __restrict__ X, const float* __restrict__ Win) {
    __shared__ float As[GBK][GBM + 4];
    __shared__ float Bs[GBK][GBN + 4];

    const int tid = threadIdx.x;
    const int bm = blockIdx.y;
    const int bn = blockIdx.x;
    const float* Xb = X   + (size_t)bm * GBM * FDIM;
    const float* Wb = Win + (size_t)bn * GBN * FDIM;

    const int ty = tid >> 4;
    const int tx = tid & 15;
    const int lrow = tid >> 3;
    const int lcol = (tid & 7) * 4;

    float acc[8][8] = {};

    for (int k0 = 0; k0 < FDIM; k0 += GBK) {
        #pragma unroll
        for (int p = 0; p < 4; p++) {
            int r = lrow + p * 32;
            float4 va = *(const float4*)(Xb + (size_t)r * FDIM + k0 + lcol);
            As[lcol + 0][r] = va.x; As[lcol + 1][r] = va.y;
            As[lcol + 2][r] = va.z; As[lcol + 3][r] = va.w;
            float4 vb = *(const float4*)(Wb + (size_t)r * FDIM + k0 + lcol);
            Bs[lcol + 0][r] = vb.x; Bs[lcol + 1][r] = vb.y;
            Bs[lcol + 2][r] = vb.z; Bs[lcol + 3][r] = vb.w;
        }
        __syncthreads();

        #pragma unroll
        for (int k = 0; k < GBK; k++) {
            float af[8], bf[8];
            *(float4*)(af)     = *(const float4*)&As[k][ty * 8];
            *(float4*)(af + 4) = *(const float4*)&As[k][ty * 8 + 4];
            *(float4*)(bf)     = *(const float4*)&Bs[k][tx * 8];
            *(float4*)(bf + 4) = *(const float4*)&Bs[k][tx * 8 + 4];
            #pragma unroll
            for (int i = 0; i < 8; i++)
                #pragma unroll
                for (int j = 0; j < 8; j++)
                    acc[i][j] += af[i] * bf[j];
        }
        __syncthreads();
    }

    float* C = g_iin + (size_t)(bm * GBM) * HDIM + bn * GBN;
    #pragma unroll
    for (int i = 0; i < 8; i++) {
        float4 v0, v1;
        v0.x = acc[i][0]; v0.y = acc[i][1]; v0.z = acc[i][2]; v0.w = acc[i][3];
        v1.x = acc[i][4]; v1.y = acc[i][5]; v1.z = acc[i][6]; v1.w = acc[i][7];
        float* Crow = C + (size_t)(ty * 8 + i) * HDIM + tx * 8;
        *(float4*)(Crow)     = v0;
        *(float4*)(Crow + 4) = v1;
    }
}

// ---------------------------------------------------------------------------
// SNN kernel. CTA = (group g, slice s). W_recT slice (512x64) in SMEM.
// R4 structure; exchange uses per-CTA flag stores (no atomic) + single poller.
// SMEM layout (bytes):
//   w_s     [512*64 f]  @0       131072
//   s_list  [8][512 i]  @131072   16384
//   s_mask  [64 u64]    @147456     512
//   s_half  [16 u32]    @147968      64
//   s_n     [8 i]       @148032      32   -> total 148064 (pad 148096)
// ---------------------------------------------------------------------------
#define SNN_SMEM 148096

__global__ void __launch_bounds__(512, 1) snn_kernel() {
    extern __shared__ char sh[];
    float*              w_s    = (float*)sh;
    int*                s_list = (int*)(sh + 131072);
    unsigned long long* s_mask = (unsigned long long*)(sh + 147456);
    unsigned*           s_half = (unsigned*)(sh + 147968);
    int*                s_n    = (int*)(sh + 148032);

    const int g    = blockIdx.x >> 3;
    const int s    = blockIdx.x & 7;
    const int tid  = threadIdx.x;
    const int warp = tid >> 5;
    const int lane = tid & 31;
    const int b    = warp >> 1;                 // local batch 0..7
    const int d    = ((warp & 1) << 5) + lane;  // dst 0..63

    // stage W_recT slice: w_s[h][d] = g_wrecT[h][s*64+d]
    for (int idx = tid; idx < HDIM * DSTW; idx += 512)
        w_s[idx] = g_wrecT[((idx >> 6) << 9) + (s << 6) + (idx & 63)];
    if (tid < 8) s_n[tid] = 0;
    __syncthreads();

    const int gb = (g << 3) + b;
    float v = 0.f, ii = 0.f, aa = 0.f;
    const float* iin = g_iin + (size_t)gb * HDIM + (s << 6) + d;
    const char*  wp  = (const char*)w_s + ((size_t)d << 2);
    const int*   lp  = s_list + (b << 9);

    for (int t = 0; t < T_STEPS; t++) {
        float ic = __ldg(iin + (size_t)t * (BATCH * HDIM));

        // ---- SMEM gather over this batch's offset list (prev step) ----
        const int nb = s_n[b];
        float a0 = 0.f, a1 = 0.f, a2 = 0.f, a3 = 0.f;
        int j = 0;
        for (; j + 4 <= nb; j += 4) {
            int4 o = *(const int4*)(lp + j);
            a0 += *(const float*)(wp + o.x);
            a1 += *(const float*)(wp + o.y);
            a2 += *(const float*)(wp + o.z);
            a3 += *(const float*)(wp + o.w);
        }
        for (; j < nb; j++)
            a0 += *(const float*)(wp + lp[j]);
        float rec = ((a0 + a1) + (a2 + a3));

        // ---- LIF-AdEx update (grouping mirrors the JAX reference) ----
        float dv   = 0.1f * ((((0.f - v) + 0.5f * expf((v - 1.f) * 2.f)) + ii) - aa);
        float vdec = v + dv;
        float idec = ii - 0.2f * ii;
        float adec = aa + 0.002f * (4.f * v - aa);
        int   z    = (vdec - 1.f) > 0.f;
        v  = z ? 0.f : vdec;
        ii = (idec + ic) + rec;
        aa = adec + (z ? 0.02f : 0.f);

        // ---- pack spike bits ----
        unsigned bal = __ballot_sync(0xffffffffu, z);
        if (lane == 0) s_half[warp] = bal;
        __syncthreads();                         // (A) gather reads + s_half done

        // ---- publish masks + flag (all warp 0; no atomic) ----
        if (warp == 0) {
            if (lane < 8) {
                unsigned long long m64 =
                    (unsigned long long)s_half[lane << 1] |
                    ((unsigned long long)s_half[(lane << 1) + 1] << 32);
                g_zall[(((size_t)t * NG + g) * GSZ + lane) * NS + s] = m64;
            }
            __syncwarp();                        // lanes' STGs hb-before fence
            if (lane == 0) {
                __threadfence();
                *(volatile int*)&g_flag[(t * NG + g) * NS + s] = 1;
                // poll all 8 peer flags (one 32-B L2 line)
                volatile int* pf = &g_flag[(t * NG + g) * NS];
                for (;;) {
                    int done = pf[0] & pf[1] & pf[2] & pf[3]
                             & pf[4] & pf[5] & pf[6] & pf[7];
                    if (done) break;
                    __nanosleep(32);
                }
                __threadfence();
            }
        }
        __syncthreads();                         // (B) all 8 CTAs published

        // ---- fetch all 64 group masks ----
        if (tid < 64)
            s_mask[tid] = __ldcg(
                &g_zall[(((size_t)t * NG + g) * GSZ + (tid >> 3)) * NS + (tid & 7)]);
        __syncthreads();                         // (C) masks ready

        // ---- expand masks -> per-batch byte-offset lists ----
        if (tid < 64) {
            const int bb = tid >> 3, p = tid & 7;
            const unsigned long long* mb = s_mask + (bb << 3);
            int base = 0;
            #pragma unroll
            for (int q = 0; q < 7; q++)
                if (q < p) base += __popcll(mb[q]);
            unsigned long long m = mb[p];
            int* out_l = s_list + (bb << 9) + base;
            const int off0 = p << 14;            // (p*64) rows * 256 B
            while (m) {
                int bit = __ffsll(m) - 1;
                m &= m - 1;
                *out_l++ = off0 + (bit << 8);
            }
            if (p == 7) s_n[bb] = base + __popcll(mb[7]);
        }
        __syncthreads();                         // (D) lists ready for next step
    }
}

// ---------------------------------------------------------------------------
// Readout: one CTA per batch. Phase 1: warps compute y[t] from spike masks
// (4 independent load chains). Phase 2: warp 0 runs the serial IIR filter.
// ---------------------------------------------------------------------------
__global__ void __launch_bounds__(512) readout_kernel(
    const float* __restrict__ b_out, float* __restrict__ out) {
    extern __shared__ float y_buf[];            // [T_STEPS][ODIM] = 64000 B
    const int B    = blockIdx.x;
    const int tid  = threadIdx.x;
    const int warp = tid >> 5;
    const int lane = tid & 31;
    const int g    = B >> 3;
    const int bb   = B & 7;

    float bo = b_out[lane];

    for (int t = warp; t < T_STEPS; t += 16) {
        const unsigned long long* mp =
            g_zall + (((size_t)t * NG + g) * GSZ + bb) * NS;
        float y0 = 0.f, y1 = 0.f, y2 = 0.f, y3 = 0.f;
        #pragma unroll
        for (int w8 = 0; w8 < 8; w8++) {
            unsigned long long m = __ldg(mp + w8);
            const float* wop = g_woutT + (w8 << 11) + lane;
            while (m) {
                int b0 = __ffsll(m) - 1; m &= m - 1;
                int b1 = -1, b2 = -1, b3 = -1;
                if (m) { b1 = __ffsll(m) - 1; m &= m - 1; }
                if (m) { b2 = __ffsll(m) - 1; m &= m - 1; }
                if (m) { b3 = __ffsll(m) - 1; m &= m - 1; }
                y0 += wop[b0 << 5];
                if (b1 >= 0) y1 += wop[b1 << 5];
                if (b2 >= 0) y2 += wop[b2 << 5];
                if (b3 >= 0) y3 += wop[b3 << 5];
            }
        }
        y_buf[t * ODIM + lane] = ((y0 + y1) + (y2 + y3)) + bo;
    }
    __syncthreads();

    if (warp == 0) {
        float o = y_buf[lane];                   // o0 = y[0]
        out[(size_t)B * ODIM + lane] = o;
        for (int t = 1; t < T_STEPS; t++) {
            float y = y_buf[t * ODIM + lane];
            o = o + 0.2231435511314f * (y - o);
            out[((size_t)t * BATCH + B) * ODIM + lane] = o;
        }
    }
}

// ---------------------------------------------------------------------------
extern "C" void kernel_launch(void* const* d_in, const int* in_sizes, int n_in,
                              void* d_out, int out_size) {
    const float* x     = (const float*)d_in[0];  // (T,B,F)
    const float* W_in  = (const float*)d_in[1];  // (H,F)
    const float* W_rec = (const float*)d_in[2];  // (H,H)
    const float* W_out = (const float*)d_in[3];  // (O,H)
    const float* b_out = (const float*)d_in[4];  // (O,)
    float* out = (float*)d_out;                  // (T,B,O)

    static const int RDO_SMEM = T_STEPS * ODIM * (int)sizeof(float);
    cudaFuncSetAttribute(snn_kernel,
                         cudaFuncAttributeMaxDynamicSharedMemorySize, SNN_SMEM);
    cudaFuncSetAttribute(readout_kernel,
                         cudaFuncAttributeMaxDynamicSharedMemorySize, RDO_SMEM);

    transpose_kernel<<<(HDIM * HDIM + 255) / 256, 256>>>(W_rec, W_out);

    dim3 ggrid(HDIM / GBN, (T_STEPS * BATCH) / GBM);  // (4, 500)
    gemm_iin_kernel<<<ggrid, 256>>>(x, W_in);

    snn_kernel<<<NG * NS, 512, SNN_SMEM>>>();

    readout_kernel<<<BATCH, 512, RDO_SMEM>>>(b_out, out);
}

// round 10
// speedup vs baseline: 2.3185x; 2.3185x over previous
#include <cuda_runtime.h>
#include <math.h>

#define T_STEPS 500
#define BATCH   128
#define FDIM    128
#define HDIM    512
#define ODIM    32

#define NGG  8     // batch groups
#define GSZ  16    // batches per group
#define NS   8     // H slices = CTAs per group
#define DSTW 64    // dst neurons per slice
#define NSNN (NGG * NS)          // 64 SNN CTAs

#define GBM 128
#define GBN 256
#define GBK 32
#define NGEMM (T_STEPS * (HDIM / GBN))   // 1000 GEMM CTAs (2 per t)

// Device-global scratch (sanctioned allocation-free path)
__device__ float g_iin[T_STEPS * BATCH * HDIM];          // x @ W_in^T
__device__ float g_wrecT[HDIM * HDIM];                   // W_rec^T [src][dst]
__device__ float g_woutT[HDIM * ODIM];                   // W_out^T [h][o]
__device__ unsigned long long g_zall[T_STEPS * NGG * NS * GSZ];  // spike masks
__device__ int   g_sync[T_STEPS * NGG];                  // per-(t,group) barrier
__device__ int   g_cnt[T_STEPS];                         // GEMM tiles done per t

// ---------------------------------------------------------------------------
// Transposes + zero per-replay counters
// ---------------------------------------------------------------------------
__global__ void transpose_kernel(const float* __restrict__ W_rec,
                                 const float* __restrict__ W_out) {
    int idx = blockIdx.x * blockDim.x + threadIdx.x;
    if (idx < HDIM * HDIM) {
        int r = idx / HDIM, c = idx % HDIM;
        g_wrecT[c * HDIM + r] = W_rec[idx];
    }
    if (idx < ODIM * HDIM) {
        int o = idx / HDIM, h = idx % HDIM;
        g_woutT[h * ODIM + o] = W_out[idx];
    }
    if (idx < T_STEPS * NGG) g_sync[idx] = 0;
    if (idx < T_STEPS)       g_cnt[idx]  = 0;
}

// ---------------------------------------------------------------------------
// Fused kernel.
//   bid <  NSNN : persistent SNN CTA (group g, slice s; 16 batches, 2/thread)
//   bid >= NSNN : GEMM producer tile (t = gid>>1, n-tile = gid&1)
// SMEM (dynamic, 165120 B) overlaid:
//   SNN:  w_s[512*64 f] @0 | s_list[16][512 i] @131072 | s_mask[128 u64]
//         @163840 | s_halfA[16 u32] @164864 | s_halfB @164928 | s_n[16 i] @164992
//   GEMM: As[32][136 f] @0 | Bs[32][264 f] @17408   (51200 B total)
// ---------------------------------------------------------------------------
#define SNN_SMEM 165120

__global__ void __launch_bounds__(512, 1) fused_kernel(
    const float* __restrict__ X, const float* __restrict__ Win) {
    extern __shared__ char sh[];
    const int tid = threadIdx.x;

    if (blockIdx.x >= NSNN) {
        // ==================== GEMM producer ====================
        float (*As)[136] = (float (*)[136])sh;
        float (*Bs)[264] = (float (*)[264])(sh + 17408);
        const int gid = blockIdx.x - NSNN;
        const int bm  = gid >> 1;               // timestep t
        const int bn  = gid & 1;
        const float* Xb = X   + (size_t)bm * GBM * FDIM;
        const float* Wb = Win + (size_t)bn * GBN * FDIM;

        const int ty = tid >> 5;                // 0..15 (8 rows each)
        const int tx = tid & 31;                // 0..31 (8 cols each)
        const int arow = tid >> 2, acol = (tid & 3) * 8;
        const int brow = tid >> 1, bcol = (tid & 1) * 16;

        float acc[8][8] = {};
        for (int k0 = 0; k0 < FDIM; k0 += GBK) {
            #pragma unroll
            for (int u = 0; u < 2; u++) {
                float4 va = *(const float4*)(Xb + (size_t)arow * FDIM + k0 + acol + u * 4);
                As[acol + u * 4 + 0][arow] = va.x; As[acol + u * 4 + 1][arow] = va.y;
                As[acol + u * 4 + 2][arow] = va.z; As[acol + u * 4 + 3][arow] = va.w;
            }
            #pragma unroll
            for (int u = 0; u < 4; u++) {
                float4 vb = *(const float4*)(Wb + (size_t)brow * FDIM + k0 + bcol + u * 4);
                Bs[bcol + u * 4 + 0][brow] = vb.x; Bs[bcol + u * 4 + 1][brow] = vb.y;
                Bs[bcol + u * 4 + 2][brow] = vb.z; Bs[bcol + u * 4 + 3][brow] = vb.w;
            }
            __syncthreads();
            #pragma unroll
            for (int k = 0; k < GBK; k++) {
                float af[8], bf[8];
                *(float4*)(af)     = *(const float4*)&As[k][ty * 8];
                *(float4*)(af + 4) = *(const float4*)&As[k][ty * 8 + 4];
                *(float4*)(bf)     = *(const float4*)&Bs[k][tx * 8];
                *(float4*)(bf + 4) = *(const float4*)&Bs[k][tx * 8 + 4];
                #pragma unroll
                for (int i = 0; i < 8; i++)
                    #pragma unroll
                    for (int j = 0; j < 8; j++)
                        acc[i][j] += af[i] * bf[j];
            }
            __syncthreads();
        }
        float* C = g_iin + (size_t)(bm * GBM) * HDIM + bn * GBN;
        #pragma unroll
        for (int i = 0; i < 8; i++) {
            float4 v0, v1;
            v0.x = acc[i][0]; v0.y = acc[i][1]; v0.z = acc[i][2]; v0.w = acc[i][3];
            v1.x = acc[i][4]; v1.y = acc[i][5]; v1.z = acc[i][6]; v1.w = acc[i][7];
            float* Crow = C + (size_t)(ty * 8 + i) * HDIM + tx * 8;
            *(float4*)(Crow)     = v0;
            *(float4*)(Crow + 4) = v1;
        }
        __threadfence();
        __syncthreads();
        if (tid == 0) atomicAdd(&g_cnt[bm], 1);   // 2 tiles per t
        return;
    }

    // ==================== SNN consumer ====================
    float*              w_s    = (float*)sh;
    int*                s_list = (int*)(sh + 131072);
    unsigned long long* s_mask = (unsigned long long*)(sh + 163840);
    unsigned*           s_halfA = (unsigned*)(sh + 164864);
    unsigned*           s_halfB = (unsigned*)(sh + 164928);
    int*                s_n    = (int*)(sh + 164992);

    const int g    = blockIdx.x >> 3;
    const int s    = blockIdx.x & 7;
    const int warp = tid >> 5;
    const int lane = tid & 31;
    const int q    = warp >> 1;                 // batches q (A) and q+8 (B)
    const int d    = ((warp & 1) << 5) + lane;  // dst 0..63

    // stage W_recT slice: w_s[h][d] = g_wrecT[h][s*64+d]
    for (int idx = tid; idx < HDIM * DSTW; idx += 512)
        w_s[idx] = g_wrecT[((idx >> 6) << 9) + (s << 6) + (idx & 63)];
    if (tid < 16) s_n[tid] = 0;
    __syncthreads();

    float vA = 0.f, iiA = 0.f, aaA = 0.f;
    float vB = 0.f, iiB = 0.f, aaB = 0.f;
    const float* iinA = g_iin + (size_t)((g << 4) + q)     * HDIM + (s << 6) + d;
    const float* iinB = g_iin + (size_t)((g << 4) + q + 8) * HDIM + (s << 6) + d;
    const char*  wp   = (const char*)w_s + ((size_t)d << 2);
    const int*   lpA  = s_list + (q << 9);
    const int*   lpB  = s_list + ((q + 8) << 9);

    // wait for i_in[0] (GEMM ramp)
    if (tid == 0) {
        while (*(volatile int*)&g_cnt[0] < 2) __nanosleep(64);
        __threadfence();
    }
    __syncthreads();

    for (int t = 0; t < T_STEPS; t++) {
        float icA = __ldg(iinA + (size_t)t * (BATCH * HDIM));
        float icB = __ldg(iinB + (size_t)t * (BATCH * HDIM));

        // ---- SMEM gathers (batch A then batch B) ----
        float recA, recB;
        {
            const int nb = s_n[q];
            float a0 = 0.f, a1 = 0.f, a2 = 0.f, a3 = 0.f;
            int j = 0;
            for (; j + 4 <= nb; j += 4) {
                int4 o = *(const int4*)(lpA + j);
                a0 += *(const float*)(wp + o.x);
                a1 += *(const float*)(wp + o.y);
                a2 += *(const float*)(wp + o.z);
                a3 += *(const float*)(wp + o.w);
            }
            for (; j < nb; j++)
                a0 += *(const float*)(wp + lpA[j]);
            recA = ((a0 + a1) + (a2 + a3));
        }
        {
            const int nb = s_n[q + 8];
            float a0 = 0.f, a1 = 0.f, a2 = 0.f, a3 = 0.f;
            int j = 0;
            for (; j + 4 <= nb; j += 4) {
                int4 o = *(const int4*)(lpB + j);
                a0 += *(const float*)(wp + o.x);
                a1 += *(const float*)(wp + o.y);
                a2 += *(const float*)(wp + o.z);
                a3 += *(const float*)(wp + o.w);
            }
            for (; j < nb; j++)
                a0 += *(const float*)(wp + lpB[j]);
            recB = ((a0 + a1) + (a2 + a3));
        }

        // ---- LIF-AdEx updates (grouping mirrors the JAX reference) ----
        float dvA   = 0.1f * ((((0.f - vA) + 0.5f * expf((vA - 1.f) * 2.f)) + iiA) - aaA);
        float vdecA = vA + dvA;
        float idecA = iiA - 0.2f * iiA;
        float adecA = aaA + 0.002f * (4.f * vA - aaA);
        int   zA    = (vdecA - 1.f) > 0.f;
        vA  = zA ? 0.f : vdecA;
        iiA = (idecA + icA) + recA;
        aaA = adecA + (zA ? 0.02f : 0.f);

        float dvB   = 0.1f * ((((0.f - vB) + 0.5f * expf((vB - 1.f) * 2.f)) + iiB) - aaB);
        float vdecB = vB + dvB;
        float idecB = iiB - 0.2f * iiB;
        float adecB = aaB + 0.002f * (4.f * vB - aaB);
        int   zB    = (vdecB - 1.f) > 0.f;
        vB  = zB ? 0.f : vdecB;
        iiB = (idecB + icB) + recB;
        aaB = adecB + (zB ? 0.02f : 0.f);

        // ---- pack spike bits ----
        unsigned balA = __ballot_sync(0xffffffffu, zA);
        unsigned balB = __ballot_sync(0xffffffffu, zB);
        if (lane == 0) { s_halfA[warp] = balA; s_halfB[warp] = balB; }
        __syncthreads();                         // (A) gather reads + halves done

        // ---- publish 16 masks (one coalesced 128-B store) + R4 barrier ----
        if (warp == 0) {
            if (lane < 16) {
                int bb = lane;
                unsigned long long m64;
                if (bb < 8)
                    m64 = (unsigned long long)s_halfA[bb << 1] |
                          ((unsigned long long)s_halfA[(bb << 1) + 1] << 32);
                else {
                    int c = bb - 8;
                    m64 = (unsigned long long)s_halfB[c << 1] |
                          ((unsigned long long)s_halfB[(c << 1) + 1] << 32);
                }
                g_zall[(((size_t)t * NGG + g) * NS + s) * GSZ + bb] = m64;
                __threadfence();
            }
            __syncwarp();
            if (lane == 0) {
                atomicAdd(&g_sync[t * NGG + g], 1);
                volatile int* pf = &g_sync[t * NGG + g];
                volatile int* pc = &g_cnt[t + 1];
                const int need = (t + 1 < T_STEPS) ? 2 : 0;
                for (;;) {
                    if (*pf >= NS && (need == 0 || *pc >= need)) break;
                    __nanosleep(32);
                }
                __threadfence();
            }
        }
        __syncthreads();                         // (B) all 8 CTAs published

        // ---- fetch all 128 group masks ([slice][batch], coalesced) ----
        if (tid < 128)
            s_mask[tid] = __ldcg(
                &g_zall[(((size_t)t * NGG + g) * NS + (tid >> 4)) * GSZ + (tid & 15)]);
        __syncthreads();                         // (C) masks ready

        // ---- expand masks -> per-batch byte-offset lists ----
        if (tid < 128) {
            const int bb = tid >> 3, p = tid & 7;
            int base = 0;
            #pragma unroll
            for (int u = 0; u < 7; u++)
                if (u < p) base += __popcll(s_mask[(u << 4) + bb]);
            unsigned long long m = s_mask[(p << 4) + bb];
            int* out_l = s_list + (bb << 9) + base;
            const int off0 = p << 14;            // (p*64) rows * 256 B
            while (m) {
                int bit = __ffsll(m) - 1;
                m &= m - 1;
                *out_l++ = off0 + (bit << 8);
            }
            if (p == 7) s_n[bb] = base + __popcll(s_mask[(7 << 4) + bb]);
        }
        __syncthreads();                         // (D) lists ready for next step
    }
}

// ---------------------------------------------------------------------------
// Readout: one CTA per batch. Warps compute y[t] from spike masks
// (4 independent load chains); warp 0 runs the serial IIR filter.
// ---------------------------------------------------------------------------
__global__ void __launch_bounds__(512) readout_kernel(
    const float* __restrict__ b_out, float* __restrict__ out) {
    extern __shared__ float y_buf[];            // [T_STEPS][ODIM] = 64000 B
    const int B    = blockIdx.x;
    const int tid  = threadIdx.x;
    const int warp = tid >> 5;
    const int lane = tid & 31;
    const int g    = B >> 4;
    const int bb   = B & 15;

    float bo = b_out[lane];

    for (int t = warp; t < T_STEPS; t += 16) {
        const unsigned long long* mp =
            g_zall + ((size_t)t * NGG + g) * NS * GSZ + bb;
        float y0 = 0.f, y1 = 0.f, y2 = 0.f, y3 = 0.f;
        #pragma unroll
        for (int w8 = 0; w8 < 8; w8++) {
            unsigned long long m = __ldg(mp + w8 * GSZ);
            const float* wop = g_woutT + (w8 << 11) + lane;
            while (m) {
                int b0 = __ffsll(m) - 1; m &= m - 1;
                int b1 = -1, b2 = -1, b3 = -1;
                if (m) { b1 = __ffsll(m) - 1; m &= m - 1; }
                if (m) { b2 = __ffsll(m) - 1; m &= m - 1; }
                if (m) { b3 = __ffsll(m) - 1; m &= m - 1; }
                y0 += wop[b0 << 5];
                if (b1 >= 0) y1 += wop[b1 << 5];
                if (b2 >= 0) y2 += wop[b2 << 5];
                if (b3 >= 0) y3 += wop[b3 << 5];
            }
        }
        y_buf[t * ODIM + lane] = ((y0 + y1) + (y2 + y3)) + bo;
    }
    __syncthreads();

    if (warp == 0) {
        float o = y_buf[lane];                   // o0 = y[0]
        out[(size_t)B * ODIM + lane] = o;
        for (int t = 1; t < T_STEPS; t++) {
            float y = y_buf[t * ODIM + lane];
            o = o + 0.2231435511314f * (y - o);
            out[((size_t)t * BATCH + B) * ODIM + lane] = o;
        }
    }
}

// ---------------------------------------------------------------------------
extern "C" void kernel_launch(void* const* d_in, const int* in_sizes, int n_in,
                              void* d_out, int out_size) {
    const float* x     = (const float*)d_in[0];  // (T,B,F)
    const float* W_in  = (const float*)d_in[1];  // (H,F)
    const float* W_rec = (const float*)d_in[2];  // (H,H)
    const float* W_out = (const float*)d_in[3];  // (O,H)
    const float* b_out = (const float*)d_in[4];  // (O,)
    float* out = (float*)d_out;                  // (T,B,O)

    static const int RDO_SMEM = T_STEPS * ODIM * (int)sizeof(float);
    cudaFuncSetAttribute(fused_kernel,
                         cudaFuncAttributeMaxDynamicSharedMemorySize, SNN_SMEM);
    cudaFuncSetAttribute(readout_kernel,
                         cudaFuncAttributeMaxDynamicSharedMemorySize, RDO_SMEM);

    transpose_kernel<<<(HDIM * HDIM + 255) / 256, 256>>>(W_rec, W_out);

    fused_kernel<<<NSNN + NGEMM, 512, SNN_SMEM>>>(x, W_in);

    readout_kernel<<<BATCH, 512, RDO_SMEM>>>(b_out, out);
}

// round 11
// speedup vs baseline: 2.4416x; 1.0531x over previous
#include <cuda_runtime.h>
#include <math.h>

#define T_STEPS 500
#define BATCH   128
#define FDIM    128
#define HDIM    512
#define ODIM    32

#define NG   16    // batch groups
#define GSZ  8     // batches per group
#define NSL  16    // H slices = CTAs per group (32 dst each)
#define DSTW 32    // dst neurons per slice
#define NSNN (NG * NSL)          // 256 SNN CTAs, 2 per SM

#define GBM 128
#define GBN 128
#define GBK 32

// Device-global scratch (sanctioned allocation-free path)
__device__ float    g_iin[T_STEPS * BATCH * HDIM];       // x @ W_in^T
__device__ float    g_wrecT[HDIM * HDIM];                // W_rec^T [src][dst]
__device__ float    g_woutT[HDIM * ODIM];                // W_out^T [h][o]
__device__ unsigned g_zmask[T_STEPS * NG * NSL * GSZ];   // u32 spike masks
__device__ int      g_sync[T_STEPS * NG];                // per-(t,group) barrier

// ---------------------------------------------------------------------------
// Transposes + zero per-replay sync counters
// ---------------------------------------------------------------------------
__global__ void transpose_kernel(const float* __restrict__ W_rec,
                                 const float* __restrict__ W_out) {
    int idx = blockIdx.x * blockDim.x + threadIdx.x;
    if (idx < HDIM * HDIM) {
        int r = idx / HDIM, c = idx % HDIM;
        g_wrecT[c * HDIM + r] = W_rec[idx];
    }
    if (idx < ODIM * HDIM) {
        int o = idx / HDIM, h = idx % HDIM;
        g_woutT[h * ODIM + o] = W_out[idx];
    }
    if (idx < T_STEPS * NG) g_sync[idx] = 0;
}

// ---------------------------------------------------------------------------
// GEMM: g_iin[m,n] = sum_k X[m,k] * W_in[n,k]   (verbatim — verified)
// ---------------------------------------------------------------------------
__global__ void __launch_bounds__(256) gemm_iin_kernel(
    const float* __restrict__ X, const float* __restrict__ Win) {
    __shared__ float As[GBK][GBM + 4];
    __shared__ float Bs[GBK][GBN + 4];

    const int tid = threadIdx.x;
    const int bm = blockIdx.y;
    const int bn = blockIdx.x;
    const float* Xb = X   + (size_t)bm * GBM * FDIM;
    const float* Wb = Win + (size_t)bn * GBN * FDIM;

    const int ty = tid >> 4;
    const int tx = tid & 15;
    const int lrow = tid >> 3;
    const int lcol = (tid & 7) * 4;

    float acc[8][8] = {};

    for (int k0 = 0; k0 < FDIM; k0 += GBK) {
        #pragma unroll
        for (int p = 0; p < 4; p++) {
            int r = lrow + p * 32;
            float4 va = *(const float4*)(Xb + (size_t)r * FDIM + k0 + lcol);
            As[lcol + 0][r] = va.x; As[lcol + 1][r] = va.y;
            As[lcol + 2][r] = va.z; As[lcol + 3][r] = va.w;
            float4 vb = *(const float4*)(Wb + (size_t)r * FDIM + k0 + lcol);
            Bs[lcol + 0][r] = vb.x; Bs[lcol + 1][r] = vb.y;
            Bs[lcol + 2][r] = vb.z; Bs[lcol + 3][r] = vb.w;
        }
        __syncthreads();

        #pragma unroll
        for (int k = 0; k < GBK; k++) {
            float af[8], bf[8];
            *(float4*)(af)     = *(const float4*)&As[k][ty * 8];
            *(float4*)(af + 4) = *(const float4*)&As[k][ty * 8 + 4];
            *(float4*)(bf)     = *(const float4*)&Bs[k][tx * 8];
            *(float4*)(bf + 4) = *(const float4*)&Bs[k][tx * 8 + 4];
            #pragma unroll
            for (int i = 0; i < 8; i++)
                #pragma unroll
                for (int j = 0; j < 8; j++)
                    acc[i][j] += af[i] * bf[j];
        }
        __syncthreads();
    }

    float* C = g_iin + (size_t)(bm * GBM) * HDIM + bn * GBN;
    #pragma unroll
    for (int i = 0; i < 8; i++) {
        float4 v0, v1;
        v0.x = acc[i][0]; v0.y = acc[i][1]; v0.z = acc[i][2]; v0.w = acc[i][3];
        v1.x = acc[i][4]; v1.y = acc[i][5]; v1.z = acc[i][6]; v1.w = acc[i][7];
        float* Crow = C + (size_t)(ty * 8 + i) * HDIM + tx * 8;
        *(float4*)(Crow)     = v0;
        *(float4*)(Crow + 4) = v1;
    }
}

// ---------------------------------------------------------------------------
// SNN kernel, occupancy 2. CTA = (slice s = bid>>4, group g = bid&15):
// consecutive bids (co-resident on one SM) belong to DIFFERENT groups, so one
// CTA's gather overlaps the other's exchange stall.
// 256 threads: warp w = batch w (8 warps), lane = dst neuron in slice (32).
// SMEM layout (bytes):
//   w_s     [512*32 f]  @0       65536   (w_s[h][d] = W_rec^T[h][s*32+d])
//   s_list  [8][512 i]  @65536   16384
//   s_mask  [128 u32]   @81920     512   ([slice][batch])
//   s_n     [8 i]       @82432      32   -> total 82464 (pad 82560)
// ---------------------------------------------------------------------------
#define SNN_SMEM 82560

__global__ void __launch_bounds__(256, 2) snn_kernel() {
    extern __shared__ char sh[];
    float*    w_s    = (float*)sh;
    int*      s_list = (int*)(sh + 65536);
    unsigned* s_mask = (unsigned*)(sh + 81920);
    int*      s_n    = (int*)(sh + 82432);

    const int s    = blockIdx.x >> 4;           // slice 0..15
    const int g    = blockIdx.x & 15;           // group 0..15
    const int tid  = threadIdx.x;
    const int warp = tid >> 5;                  // batch 0..7
    const int lane = tid & 31;                  // dst 0..31

    // stage W_recT slice: w_s[h][d] = g_wrecT[h][s*32+d]
    for (int idx = tid; idx < HDIM * DSTW; idx += 256)
        w_s[idx] = g_wrecT[((idx >> 5) << 9) + (s << 5) + (idx & 31)];
    if (tid < 8) s_n[tid] = 0;
    __syncthreads();

    const int gb = (g << 3) + warp;             // global batch
    float v = 0.f, ii = 0.f, aa = 0.f;
    const float* iin = g_iin + (size_t)gb * HDIM + (s << 5) + lane;
    const char*  wp  = (const char*)w_s + ((size_t)lane << 2);
    const int*   lp  = s_list + (warp << 9);

    for (int t = 0; t < T_STEPS; t++) {
        float ic = __ldg(iin + (size_t)t * (BATCH * HDIM));

        // ---- SMEM gather over this batch's offset list (prev step) ----
        const int nb = s_n[warp];
        float a0 = 0.f, a1 = 0.f, a2 = 0.f, a3 = 0.f;
        int j = 0;
        for (; j + 4 <= nb; j += 4) {
            int4 o = *(const int4*)(lp + j);
            a0 += *(const float*)(wp + o.x);
            a1 += *(const float*)(wp + o.y);
            a2 += *(const float*)(wp + o.z);
            a3 += *(const float*)(wp + o.w);
        }
        for (; j < nb; j++)
            a0 += *(const float*)(wp + lp[j]);
        float rec = ((a0 + a1) + (a2 + a3));

        // ---- LIF-AdEx update (grouping mirrors the JAX reference) ----
        float dv   = 0.1f * ((((0.f - v) + 0.5f * expf((v - 1.f) * 2.f)) + ii) - aa);
        float vdec = v + dv;
        float idec = ii - 0.2f * ii;
        float adec = aa + 0.002f * (4.f * v - aa);
        int   z    = (vdec - 1.f) > 0.f;
        v  = z ? 0.f : vdec;
        ii = (idec + ic) + rec;
        aa = adec + (z ? 0.02f : 0.f);

        // ---- publish: ballot IS the 32-bit slice mask for batch `warp` ----
        unsigned bal = __ballot_sync(0xffffffffu, z);
        if (lane == 0) {
            g_zmask[(((size_t)t * NG + g) * NSL + s) * GSZ + warp] = bal;
            __threadfence();
        }
        __syncthreads();                         // (A) gather reads + STGs done

        // ---- group barrier: R4 protocol (atomicAdd + single-word poll) ----
        if (tid == 0) {
            atomicAdd(&g_sync[t * NG + g], 1);
            volatile int* pf = &g_sync[t * NG + g];
            while (*pf < NSL) __nanosleep(32);
            __threadfence();
        }
        __syncthreads();                         // (B) all 16 CTAs published

        // ---- fetch all 128 group masks (512 B, coalesced) ----
        if (tid < 128)
            s_mask[tid] = __ldcg(&g_zmask[((size_t)t * NG + g) * (NSL * GSZ) + tid]);
        __syncthreads();                         // (C) masks ready

        // ---- expand masks -> per-batch byte-offset lists ----
        if (tid < 128) {
            const int bb = tid >> 4, p = tid & 15;
            int base = 0;
            #pragma unroll
            for (int q = 0; q < 15; q++)
                if (q < p) base += __popc(s_mask[(q << 3) + bb]);
            unsigned m = s_mask[(p << 3) + bb];
            int* out_l = s_list + (bb << 9) + base;
            const int off0 = p << 12;            // (p*32) rows * 128 B
            while (m) {
                int bit = __ffs(m) - 1;
                m &= m - 1;
                *out_l++ = off0 + (bit << 7);    // row h -> h*128 bytes
            }
            if (p == 15) s_n[bb] = base + __popc(s_mask[(15 << 3) + bb]);
        }
        __syncthreads();                         // (D) lists ready for next step
    }
}

// ---------------------------------------------------------------------------
// Readout: one CTA per batch. Warps compute y[t] from u32 spike masks
// (4 independent load chains); warp 0 runs the serial IIR filter.
// ---------------------------------------------------------------------------
__global__ void __launch_bounds__(512) readout_kernel(
    const float* __restrict__ b_out, float* __restrict__ out) {
    extern __shared__ float y_buf[];            // [T_STEPS][ODIM] = 64000 B
    const int B    = blockIdx.x;
    const int tid  = threadIdx.x;
    const int warp = tid >> 5;
    const int lane = tid & 31;
    const int g    = B >> 3;
    const int bb   = B & 7;

    float bo = b_out[lane];

    for (int t = warp; t < T_STEPS; t += 16) {
        const unsigned* mp =
            g_zmask + ((size_t)t * NG + g) * (NSL * GSZ) + bb;
        float y0 = 0.f, y1 = 0.f, y2 = 0.f, y3 = 0.f;
        #pragma unroll
        for (int p = 0; p < NSL; p++) {
            unsigned m = __ldg(mp + (p << 3));
            const float* wop = g_woutT + (p << 10) + lane;  // rows p*32..
            while (m) {
                int b0 = __ffs(m) - 1; m &= m - 1;
                int b1 = -1, b2 = -1, b3 = -1;
                if (m) { b1 = __ffs(m) - 1; m &= m - 1; }
                if (m) { b2 = __ffs(m) - 1; m &= m - 1; }
                if (m) { b3 = __ffs(m) - 1; m &= m - 1; }
                y0 += wop[b0 << 5];
                if (b1 >= 0) y1 += wop[b1 << 5];
                if (b2 >= 0) y2 += wop[b2 << 5];
                if (b3 >= 0) y3 += wop[b3 << 5];
            }
        }
        y_buf[t * ODIM + lane] = ((y0 + y1) + (y2 + y3)) + bo;
    }
    __syncthreads();

    if (warp == 0) {
        float o = y_buf[lane];                   // o0 = y[0]
        out[(size_t)B * ODIM + lane] = o;
        for (int t = 1; t < T_STEPS; t++) {
            float y = y_buf[t * ODIM + lane];
            o = o + 0.2231435511314f * (y - o);
            out[((size_t)t * BATCH + B) * ODIM + lane] = o;
        }
    }
}

// ---------------------------------------------------------------------------
extern "C" void kernel_launch(void* const* d_in, const int* in_sizes, int n_in,
                              void* d_out, int out_size) {
    const float* x     = (const float*)d_in[0];  // (T,B,F)
    const float* W_in  = (const float*)d_in[1];  // (H,F)
    const float* W_rec = (const float*)d_in[2];  // (H,H)
    const float* W_out = (const float*)d_in[3];  // (O,H)
    const float* b_out = (const float*)d_in[4];  // (O,)
    float* out = (float*)d_out;                  // (T,B,O)

    static const int RDO_SMEM = T_STEPS * ODIM * (int)sizeof(float);
    cudaFuncSetAttribute(snn_kernel,
                         cudaFuncAttributeMaxDynamicSharedMemorySize, SNN_SMEM);
    cudaFuncSetAttribute(readout_kernel,
                         cudaFuncAttributeMaxDynamicSharedMemorySize, RDO_SMEM);

    transpose_kernel<<<(HDIM * HDIM + 255) / 256, 256>>>(W_rec, W_out);

    dim3 ggrid(HDIM / GBN, (T_STEPS * BATCH) / GBM);  // (4, 500)
    gemm_iin_kernel<<<ggrid, 256>>>(x, W_in);

    snn_kernel<<<NSNN, 256, SNN_SMEM>>>();

    readout_kernel<<<BATCH, 512, RDO_SMEM>>>(b_out, out);
}

// round 12
// speedup vs baseline: 2.7865x; 1.1413x over previous
#include <cuda_runtime.h>
#include <math.h>

#define T_STEPS 500
#define BATCH   128
#define FDIM    128
#define HDIM    512
#define ODIM    32

#define NG  16     // batch groups
#define GSZ 8      // batches per group
#define NS  8      // H slices (CTAs per group)
#define DSTW 64    // dst neurons per slice

#define GBM 128
#define GBN 128
#define GBK 32

// Device-global scratch (sanctioned allocation-free path)
__device__ float g_iin[T_STEPS * BATCH * HDIM];          // x @ W_in^T
__device__ float g_wrecT[HDIM * HDIM];                   // W_rec^T [src][dst]
__device__ float g_woutT[HDIM * ODIM];                   // W_out^T [h][o]
__device__ unsigned long long g_zall[T_STEPS * NG * GSZ * NS];  // spike masks
__device__ int   g_sync[T_STEPS * NG];                   // per-(t,group) barrier

// packed fp32x2 FMA (sm_103a FFMA2; fp32-exact rounding per lane)
#define FMA_F32X2(d, a, b) \
    asm("fma.rn.f32x2 %0, %1, %2, %0;" : "+l"(d) : "l"(a), "l"(b))
#define SPLAT_F32X2(d, x) \
    asm("mov.b64 %0, {%1, %1};" : "=l"(d) : "r"(__float_as_uint(x)))

// ---------------------------------------------------------------------------
// Transposes + zero per-replay sync counters
// ---------------------------------------------------------------------------
__global__ void transpose_kernel(const float* __restrict__ W_rec,
                                 const float* __restrict__ W_out) {
    int idx = blockIdx.x * blockDim.x + threadIdx.x;
    if (idx < HDIM * HDIM) {
        int r = idx / HDIM, c = idx % HDIM;
        g_wrecT[c * HDIM + r] = W_rec[idx];
    }
    if (idx < ODIM * HDIM) {
        int o = idx / HDIM, h = idx % HDIM;
        g_woutT[h * ODIM + o] = W_out[idx];
    }
    if (idx < T_STEPS * NG) g_sync[idx] = 0;
}

// ---------------------------------------------------------------------------
// GEMM: g_iin[m,n] = sum_k X[m,k] * W_in[n,k]
// R2 tiling (proven), inner product rewritten with fma.rn.f32x2:
// 32 FMA2 + 8 splat-MOV per k instead of 64 FFMA -> ~2x fp32 throughput.
// Accumulator pairs acc[i][p] hold columns (2p, 2p+1) packed in 64 bits.
// ---------------------------------------------------------------------------
__global__ void __launch_bounds__(256) gemm_iin_kernel(
    const float* __restrict__ X, const float* __restrict__ Win) {
    __shared__ float As[GBK][GBM + 4];
    __shared__ float Bs[GBK][GBN + 4];

    const int tid = threadIdx.x;
    const int bm = blockIdx.y;
    const int bn = blockIdx.x;
    const float* Xb = X   + (size_t)bm * GBM * FDIM;
    const float* Wb = Win + (size_t)bn * GBN * FDIM;

    const int ty = tid >> 4;
    const int tx = tid & 15;
    const int lrow = tid >> 3;
    const int lcol = (tid & 7) * 4;

    unsigned long long acc[8][4] = {};   // zero bits == (0.f, 0.f)

    for (int k0 = 0; k0 < FDIM; k0 += GBK) {
        #pragma unroll
        for (int p = 0; p < 4; p++) {
            int r = lrow + p * 32;
            float4 va = *(const float4*)(Xb + (size_t)r * FDIM + k0 + lcol);
            As[lcol + 0][r] = va.x; As[lcol + 1][r] = va.y;
            As[lcol + 2][r] = va.z; As[lcol + 3][r] = va.w;
            float4 vb = *(const float4*)(Wb + (size_t)r * FDIM + k0 + lcol);
            Bs[lcol + 0][r] = vb.x; Bs[lcol + 1][r] = vb.y;
            Bs[lcol + 2][r] = vb.z; Bs[lcol + 3][r] = vb.w;
        }
        __syncthreads();

        #pragma unroll
        for (int k = 0; k < GBK; k++) {
            float af[8];
            *(float4*)(af)     = *(const float4*)&As[k][ty * 8];
            *(float4*)(af + 4) = *(const float4*)&As[k][ty * 8 + 4];
            // b columns as packed pairs (free reinterpret of the 16-B loads)
            ulonglong2 b01 = *(const ulonglong2*)&Bs[k][tx * 8];
            ulonglong2 b23 = *(const ulonglong2*)&Bs[k][tx * 8 + 4];
            #pragma unroll
            for (int i = 0; i < 8; i++) {
                unsigned long long ad;
                SPLAT_F32X2(ad, af[i]);
                FMA_F32X2(acc[i][0], ad, b01.x);
                FMA_F32X2(acc[i][1], ad, b01.y);
                FMA_F32X2(acc[i][2], ad, b23.x);
                FMA_F32X2(acc[i][3], ad, b23.y);
            }
        }
        __syncthreads();
    }

    float* C = g_iin + (size_t)(bm * GBM) * HDIM + bn * GBN;
    #pragma unroll
    for (int i = 0; i < 8; i++) {
        float* Crow = C + (size_t)(ty * 8 + i) * HDIM + tx * 8;
        ulonglong2 v0, v1;
        v0.x = acc[i][0]; v0.y = acc[i][1];
        v1.x = acc[i][2]; v1.y = acc[i][3];
        *(ulonglong2*)(Crow)     = v0;
        *(ulonglong2*)(Crow + 4) = v1;
    }
}

// ---------------------------------------------------------------------------
// SNN kernel — R4 VERBATIM (settled optimum). CTA = (group g, slice s).
// W_recT slice (512x64 fp32 = 128 KB) cached in SMEM; gathers hit SMEM only.
// Per-step cross-slice spike exchange via global bitmasks + atomic barrier.
// ---------------------------------------------------------------------------
#define SNN_SMEM 148352

__global__ void __launch_bounds__(512, 1) snn_kernel() {
    extern __shared__ char sh[];
    float*              w_s    = (float*)sh;                         // 131072 B
    int*                s_list = (int*)(sh + 131072);                // 16384 B
    unsigned long long* s_mask = (unsigned long long*)(sh + 147456); // 512 B
    int*                s_cnt  = (int*)(sh + 147968);                // 256 B
    unsigned*           s_half = (unsigned*)(sh + 148224);           // 64 B
    int*                s_n    = (int*)(sh + 148288);                // 32 B

    const int g    = blockIdx.x >> 3;
    const int s    = blockIdx.x & 7;
    const int tid  = threadIdx.x;
    const int warp = tid >> 5;
    const int lane = tid & 31;
    const int b    = warp >> 1;                 // local batch 0..7
    const int d    = ((warp & 1) << 5) + lane;  // dst 0..63

    // stage W_recT slice: w_s[h][d] = g_wrecT[h][s*64+d]
    for (int idx = tid; idx < HDIM * DSTW; idx += 512)
        w_s[idx] = g_wrecT[((idx >> 6) << 9) + (s << 6) + (idx & 63)];
    if (tid < 8) s_n[tid] = 0;
    __syncthreads();

    const int gb = (g << 3) + b;                // global batch
    float v = 0.f, ii = 0.f, aa = 0.f;
    const float* iin = g_iin + (size_t)gb * HDIM + (s << 6) + d;
    const char*  wp  = (const char*)w_s + ((size_t)d << 2);
    const int*   lp  = s_list + (b << 9);

    for (int t = 0; t < T_STEPS; t++) {
        float ic = __ldg(iin + (size_t)t * (BATCH * HDIM));

        // ---- SMEM gather over the precomputed offset list of batch b ----
        const int nb = s_n[b];
        float a0 = 0.f, a1 = 0.f, a2 = 0.f, a3 = 0.f;
        int j = 0;
        for (; j + 4 <= nb; j += 4) {
            int4 o = *(const int4*)(lp + j);
            a0 += *(const float*)(wp + o.x);
            a1 += *(const float*)(wp + o.y);
            a2 += *(const float*)(wp + o.z);
            a3 += *(const float*)(wp + o.w);
        }
        for (; j < nb; j++)
            a0 += *(const float*)(wp + lp[j]);
        float rec = ((a0 + a1) + (a2 + a3));

        // ---- LIF-AdEx update (grouping mirrors the JAX reference) ----
        float dv   = 0.1f * ((((0.f - v) + 0.5f * expf((v - 1.f) * 2.f)) + ii) - aa);
        float vdec = v + dv;
        float idec = ii - 0.2f * ii;
        float adec = aa + 0.002f * (4.f * v - aa);
        int   z    = (vdec - 1.f) > 0.f;
        v  = z ? 0.f : vdec;
        ii = (idec + ic) + rec;
        aa = adec + (z ? 0.02f : 0.f);

        // ---- pack local 64-dst spike bits ----
        unsigned bal = __ballot_sync(0xffffffffu, z);
        if (lane == 0) s_half[warp] = bal;
        __syncthreads();
        if (tid < 8) {
            unsigned long long m64 =
                (unsigned long long)s_half[tid << 1] |
                ((unsigned long long)s_half[(tid << 1) + 1] << 32);
            g_zall[(((size_t)t * NG + g) * GSZ + tid) * NS + s] = m64;
            __threadfence();
        }
        __syncthreads();                 // publishes + fences done

        // ---- group barrier (8 slice-CTAs, all co-resident) ----
        if (tid == 0) {
            atomicAdd(&g_sync[t * NG + g], 1);
            volatile int* p = &g_sync[t * NG + g];
            while (*p < NS) __nanosleep(40);
        }
        __syncthreads();

        // ---- fetch merged masks ----
        if (tid < 64)
            s_mask[tid] = __ldcg(&g_zall[(((size_t)t * NG + g) * GSZ + (tid >> 3)) * NS + (tid & 7)]);
        __syncthreads();
        if (tid < 64) s_cnt[tid] = __popcll(s_mask[tid]);
        __syncthreads();

        // ---- expand masks to per-batch byte-offset lists ----
        if (tid < 64) {
            int bb = tid >> 3, w8 = tid & 7;
            int base = 0;
            #pragma unroll
            for (int q = 0; q < 7; q++)
                if (q < w8) base += s_cnt[(bb << 3) + q];
            unsigned long long m = s_mask[tid];
            int* out_l = s_list + (bb << 9) + base;
            int off0 = w8 << 14;                  // (w8*64) rows * 256 B
            while (m) {
                int bit = __ffsll(m) - 1;
                m &= m - 1;
                *out_l++ = off0 + (bit << 8);     // row h -> h*256 bytes
            }
            if (w8 == 7) s_n[bb] = base + s_cnt[tid];
        }
        __syncthreads();
    }
}

// ---------------------------------------------------------------------------
// Readout: one CTA per batch. W_outT staged in SMEM -> the per-spike loads
// are conflict-free LDS instead of L2-latency chains. Warp 0 runs the IIR.
// SMEM: w_s [512*32 f] @0 (65536 B) | y_buf [500*32 f] @65536 (64000 B)
// ---------------------------------------------------------------------------
#define RDO_SMEM (65536 + T_STEPS * ODIM * 4)

__global__ void __launch_bounds__(512) readout_kernel(
    const float* __restrict__ b_out, float* __restrict__ out) {
    extern __shared__ char rsh[];
    float* w_s   = (float*)rsh;                  // [512][32]
    float* y_buf = (float*)(rsh + 65536);        // [500][32]
    const int B    = blockIdx.x;
    const int tid  = threadIdx.x;
    const int warp = tid >> 5;
    const int lane = tid & 31;
    const int g    = B >> 3;
    const int bb   = B & 7;

    for (int idx = tid; idx < HDIM * ODIM; idx += 512)
        w_s[idx] = g_woutT[idx];
    __syncthreads();

    float bo = b_out[lane];

    for (int t = warp; t < T_STEPS; t += 16) {
        const unsigned long long* mp =
            g_zall + (((size_t)t * NG + g) * GSZ + bb) * NS;
        float y0 = 0.f, y1 = 0.f, y2 = 0.f, y3 = 0.f;
        #pragma unroll
        for (int w8 = 0; w8 < 8; w8++) {
            unsigned long long m = __ldg(mp + w8);
            const float* wop = w_s + (w8 << 11) + lane;
            while (m) {
                int b0 = __ffsll(m) - 1; m &= m - 1;
                int b1 = -1, b2 = -1, b3 = -1;
                if (m) { b1 = __ffsll(m) - 1; m &= m - 1; }
                if (m) { b2 = __ffsll(m) - 1; m &= m - 1; }
                if (m) { b3 = __ffsll(m) - 1; m &= m - 1; }
                y0 += wop[b0 << 5];
                if (b1 >= 0) y1 += wop[b1 << 5];
                if (b2 >= 0) y2 += wop[b2 << 5];
                if (b3 >= 0) y3 += wop[b3 << 5];
            }
        }
        y_buf[t * ODIM + lane] = ((y0 + y1) + (y2 + y3)) + bo;
    }
    __syncthreads();

    if (warp == 0) {
        float o = y_buf[lane];                   // o0 = y[0]
        out[(size_t)B * ODIM + lane] = o;
        for (int t = 1; t < T_STEPS; t++) {
            float y = y_buf[t * ODIM + lane];
            o = o + 0.2231435511314f * (y - o);
            out[((size_t)t * BATCH + B) * ODIM + lane] = o;
        }
    }
}

// ---------------------------------------------------------------------------
extern "C" void kernel_launch(void* const* d_in, const int* in_sizes, int n_in,
                              void* d_out, int out_size) {
    const float* x     = (const float*)d_in[0];  // (T,B,F)
    const float* W_in  = (const float*)d_in[1];  // (H,F)
    const float* W_rec = (const float*)d_in[2];  // (H,H)
    const float* W_out = (const float*)d_in[3];  // (O,H)
    const float* b_out = (const float*)d_in[4];  // (O,)
    float* out = (float*)d_out;                  // (T,B,O)

    cudaFuncSetAttribute(snn_kernel,
                         cudaFuncAttributeMaxDynamicSharedMemorySize, SNN_SMEM);
    cudaFuncSetAttribute(readout_kernel,
                         cudaFuncAttributeMaxDynamicSharedMemorySize, RDO_SMEM);

    transpose_kernel<<<(HDIM * HDIM + 255) / 256, 256>>>(W_rec, W_out);

    dim3 ggrid(HDIM / GBN, (T_STEPS * BATCH) / GBM);  // (4, 500)
    gemm_iin_kernel<<<ggrid, 256>>>(x, W_in);

    snn_kernel<<<NG * NS, 512, SNN_SMEM>>>();

    readout_kernel<<<BATCH, 512, RDO_SMEM>>>(b_out, out);
}

// round 14
// speedup vs baseline: 2.8967x; 1.0395x over previous
#include <cuda_runtime.h>
#include <math.h>

#define T_STEPS 500
#define BATCH   128
#define FDIM    128
#define HDIM    512
#define ODIM    32

#define NG  16     // batch groups
#define GSZ 8      // batches per group
#define NS  8      // H slices (CTAs per group)
#define DSTW 64    // dst neurons per slice

#define GBM 128
#define GBN 128
#define GBK 32

// Device-global scratch (sanctioned allocation-free path)
__device__ float g_iin[T_STEPS * BATCH * HDIM];          // x @ W_in^T
__device__ float g_wrecT[HDIM * HDIM];                   // W_rec^T [src][dst]
__device__ float g_woutT[HDIM * ODIM];                   // W_out^T [h][o]
__device__ unsigned long long g_zall[T_STEPS * NG * GSZ * NS];  // spike masks
__device__ int   g_sync[T_STEPS * NG];                   // per-(t,group) barrier

// ---------------------------------------------------------------------------
// Transposes + zero per-replay sync counters
// ---------------------------------------------------------------------------
__global__ void transpose_kernel(const float* __restrict__ W_rec,
                                 const float* __restrict__ W_out) {
    int idx = blockIdx.x * blockDim.x + threadIdx.x;
    if (idx < HDIM * HDIM) {
        int r = idx / HDIM, c = idx % HDIM;
        g_wrecT[c * HDIM + r] = W_rec[idx];
    }
    if (idx < ODIM * HDIM) {
        int o = idx / HDIM, h = idx % HDIM;
        g_woutT[h * ODIM + o] = W_out[idx];
    }
    if (idx < T_STEPS * NG) g_sync[idx] = 0;
}

// ---------------------------------------------------------------------------
// GEMM: g_iin[m,n] = sum_k X[m,k] * W_in[n,k]   (R2 version — proven fastest)
// ---------------------------------------------------------------------------
__global__ void __launch_bounds__(256) gemm_iin_kernel(
    const float* __restrict__ X, const float* __restrict__ Win) {
    __shared__ float As[GBK][GBM + 4];
    __shared__ float Bs[GBK][GBN + 4];

    const int tid = threadIdx.x;
    const int bm = blockIdx.y;
    const int bn = blockIdx.x;
    const float* Xb = X   + (size_t)bm * GBM * FDIM;
    const float* Wb = Win + (size_t)bn * GBN * FDIM;

    const int ty = tid >> 4;
    const int tx = tid & 15;
    const int lrow = tid >> 3;
    const int lcol = (tid & 7) * 4;

    float acc[8][8] = {};

    for (int k0 = 0; k0 < FDIM; k0 += GBK) {
        #pragma unroll
        for (int p = 0; p < 4; p++) {
            int r = lrow + p * 32;
            float4 va = *(const float4*)(Xb + (size_t)r * FDIM + k0 + lcol);
            As[lcol + 0][r] = va.x; As[lcol + 1][r] = va.y;
            As[lcol + 2][r] = va.z; As[lcol + 3][r] = va.w;
            float4 vb = *(const float4*)(Wb + (size_t)r * FDIM + k0 + lcol);
            Bs[lcol + 0][r] = vb.x; Bs[lcol + 1][r] = vb.y;
            Bs[lcol + 2][r] = vb.z; Bs[lcol + 3][r] = vb.w;
        }
        __syncthreads();

        #pragma unroll
        for (int k = 0; k < GBK; k++) {
            float af[8], bf[8];
            *(float4*)(af)     = *(const float4*)&As[k][ty * 8];
            *(float4*)(af + 4) = *(const float4*)&As[k][ty * 8 + 4];
            *(float4*)(bf)     = *(const float4*)&Bs[k][tx * 8];
            *(float4*)(bf + 4) = *(const float4*)&Bs[k][tx * 8 + 4];
            #pragma unroll
            for (int i = 0; i < 8; i++)
                #pragma unroll
                for (int j = 0; j < 8; j++)
                    acc[i][j] += af[i] * bf[j];
        }
        __syncthreads();
    }

    float* C = g_iin + (size_t)(bm * GBM) * HDIM + bn * GBN;
    #pragma unroll
    for (int i = 0; i < 8; i++) {
        float4 v0, v1;
        v0.x = acc[i][0]; v0.y = acc[i][1]; v0.z = acc[i][2]; v0.w = acc[i][3];
        v1.x = acc[i][4]; v1.y = acc[i][5]; v1.z = acc[i][6]; v1.w = acc[i][7];
        float* Crow = C + (size_t)(ty * 8 + i) * HDIM + tx * 8;
        *(float4*)(Crow)     = v0;
        *(float4*)(Crow + 4) = v1;
    }
}

// ---------------------------------------------------------------------------
// SNN kernel — R4 structure (settled optimum), with the popcount stage merged
// into the expand phase (lists produced are byte-identical to R4; one fewer
// __syncthreads per step). Gather summation order == R4 == frozen spec.
// SMEM layout (bytes):
//   w_s     [512*64 f]  @0       131072
//   s_list  [8][512 i]  @131072   16384
//   s_mask  [64 u64]    @147456     512
//   s_half  [16 u32]    @147968      64
//   s_n     [8 i]       @148032      32   -> total 148064 (pad 148096)
// ---------------------------------------------------------------------------
#define SNN_SMEM 148096

__global__ void __launch_bounds__(512, 1) snn_kernel() {
    extern __shared__ char sh[];
    float*              w_s    = (float*)sh;
    int*                s_list = (int*)(sh + 131072);
    unsigned long long* s_mask = (unsigned long long*)(sh + 147456);
    unsigned*           s_half = (unsigned*)(sh + 147968);
    int*                s_n    = (int*)(sh + 148032);

    const int g    = blockIdx.x >> 3;
    const int s    = blockIdx.x & 7;
    const int tid  = threadIdx.x;
    const int warp = tid >> 5;
    const int lane = tid & 31;
    const int b    = warp >> 1;                 // local batch 0..7
    const int d    = ((warp & 1) << 5) + lane;  // dst 0..63

    // stage W_recT slice: w_s[h][d] = g_wrecT[h][s*64+d]
    for (int idx = tid; idx < HDIM * DSTW; idx += 512)
        w_s[idx] = g_wrecT[((idx >> 6) << 9) + (s << 6) + (idx & 63)];
    if (tid < 8) s_n[tid] = 0;
    __syncthreads();

    const int gb = (g << 3) + b;                // global batch
    float v = 0.f, ii = 0.f, aa = 0.f;
    const float* iin = g_iin + (size_t)gb * HDIM + (s << 6) + d;
    const char*  wp  = (const char*)w_s + ((size_t)d << 2);
    const int*   lp  = s_list + (b << 9);

    for (int t = 0; t < T_STEPS; t++) {
        float ic = __ldg(iin + (size_t)t * (BATCH * HDIM));

        // ---- SMEM gather over the precomputed offset list of batch b ----
        // (order frozen: position-mod-4 chains over the ascending-h list)
        const int nb = s_n[b];
        float a0 = 0.f, a1 = 0.f, a2 = 0.f, a3 = 0.f;
        int j = 0;
        for (; j + 4 <= nb; j += 4) {
            int4 o = *(const int4*)(lp + j);
            a0 += *(const float*)(wp + o.x);
            a1 += *(const float*)(wp + o.y);
            a2 += *(const float*)(wp + o.z);
            a3 += *(const float*)(wp + o.w);
        }
        for (; j < nb; j++)
            a0 += *(const float*)(wp + lp[j]);
        float rec = ((a0 + a1) + (a2 + a3));

        // ---- LIF-AdEx update (grouping mirrors the JAX reference) ----
        float dv   = 0.1f * ((((0.f - v) + 0.5f * expf((v - 1.f) * 2.f)) + ii) - aa);
        float vdec = v + dv;
        float idec = ii - 0.2f * ii;
        float adec = aa + 0.002f * (4.f * v - aa);
        int   z    = (vdec - 1.f) > 0.f;
        v  = z ? 0.f : vdec;
        ii = (idec + ic) + rec;
        aa = adec + (z ? 0.02f : 0.f);

        // ---- pack local 64-dst spike bits ----
        unsigned bal = __ballot_sync(0xffffffffu, z);
        if (lane == 0) s_half[warp] = bal;
        __syncthreads();                         // (A) gather reads + s_half done

        // ---- publish masks (R4 protocol, verbatim) ----
        if (tid < 8) {
            unsigned long long m64 =
                (unsigned long long)s_half[tid << 1] |
                ((unsigned long long)s_half[(tid << 1) + 1] << 32);
            g_zall[(((size_t)t * NG + g) * GSZ + tid) * NS + s] = m64;
            __threadfence();
        }
        __syncthreads();                         // (B) publishes + fences done

        // ---- group barrier (8 slice-CTAs, all co-resident) ----
        if (tid == 0) {
            atomicAdd(&g_sync[t * NG + g], 1);
            volatile int* p = &g_sync[t * NG + g];
            while (*p < NS) __nanosleep(40);
        }
        __syncthreads();                         // barrier passed

        // ---- fetch merged masks ----
        if (tid < 64)
            s_mask[tid] = __ldcg(
                &g_zall[(((size_t)t * NG + g) * GSZ + (tid >> 3)) * NS + (tid & 7)]);
        __syncthreads();                         // (C) masks ready

        // ---- expand masks -> per-batch byte-offset lists ----
        // (prefix popcounts computed inline; lists byte-identical to R4)
        if (tid < 64) {
            const int bb = tid >> 3, w8 = tid & 7;
            const unsigned long long* mbase = s_mask + (bb << 3);
            int base = 0;
            #pragma unroll
            for (int q = 0; q < 7; q++)
                if (q < w8) base += __popcll(mbase[q]);
            unsigned long long m = mbase[w8];
            int* out_l = s_list + (bb << 9) + base;
            const int off0 = w8 << 14;            // (w8*64) rows * 256 B
            while (m) {
                int bit = __ffsll(m) - 1;
                m &= m - 1;
                *out_l++ = off0 + (bit << 8);     // row h -> h*256 bytes
            }
            if (w8 == 7) s_n[bb] = base + __popcll(mbase[7]);
        }
        __syncthreads();                         // (D) lists ready for next step
    }
}

// ---------------------------------------------------------------------------
// Readout (R11 version, measured 96 us): W_outT staged in SMEM, 4-chain scan.
// ---------------------------------------------------------------------------
#define RDO_SMEM (65536 + T_STEPS * ODIM * 4)

__global__ void __launch_bounds__(512) readout_kernel(
    const float* __restrict__ b_out, float* __restrict__ out) {
    extern __shared__ char rsh[];
    float* w_s   = (float*)rsh;                  // [512][32]
    float* y_buf = (float*)(rsh + 65536);        // [500][32]
    const int B    = blockIdx.x;
    const int tid  = threadIdx.x;
    const int warp = tid >> 5;
    const int lane = tid & 31;
    const int g    = B >> 3;
    const int bb   = B & 7;

    for (int idx = tid; idx < HDIM * ODIM; idx += 512)
        w_s[idx] = g_woutT[idx];
    __syncthreads();

    float bo = b_out[lane];

    for (int t = warp; t < T_STEPS; t += 16) {
        const unsigned long long* mp =
            g_zall + (((size_t)t * NG + g) * GSZ + bb) * NS;
        float y0 = 0.f, y1 = 0.f, y2 = 0.f, y3 = 0.f;
        #pragma unroll
        for (int w8 = 0; w8 < 8; w8++) {
            unsigned long long m = __ldg(mp + w8);
            const float* wop = w_s + (w8 << 11) + lane;
            while (m) {
                int b0 = __ffsll(m) - 1; m &= m - 1;
                int b1 = -1, b2 = -1, b3 = -1;
                if (m) { b1 = __ffsll(m) - 1; m &= m - 1; }
                if (m) { b2 = __ffsll(m) - 1; m &= m - 1; }
                if (m) { b3 = __ffsll(m) - 1; m &= m - 1; }
                y0 += wop[b0 << 5];
                if (b1 >= 0) y1 += wop[b1 << 5];
                if (b2 >= 0) y2 += wop[b2 << 5];
                if (b3 >= 0) y3 += wop[b3 << 5];
            }
        }
        y_buf[t * ODIM + lane] = ((y0 + y1) + (y2 + y3)) + bo;
    }
    __syncthreads();

    if (warp == 0) {
        float o = y_buf[lane];                   // o0 = y[0]
        out[(size_t)B * ODIM + lane] = o;
        for (int t = 1; t < T_STEPS; t++) {
            float y = y_buf[t * ODIM + lane];
            o = o + 0.2231435511314f * (y - o);
            out[((size_t)t * BATCH + B) * ODIM + lane] = o;
        }
    }
}

// ---------------------------------------------------------------------------
extern "C" void kernel_launch(void* const* d_in, const int* in_sizes, int n_in,
                              void* d_out, int out_size) {
    const float* x     = (const float*)d_in[0];  // (T,B,F)
    const float* W_in  = (const float*)d_in[1];  // (H,F)
    const float* W_rec = (const float*)d_in[2];  // (H,H)
    const float* W_out = (const float*)d_in[3];  // (O,H)
    const float* b_out = (const float*)d_in[4];  // (O,)
    float* out = (float*)d_out;                  // (T,B,O)

    cudaFuncSetAttribute(snn_kernel,
                         cudaFuncAttributeMaxDynamicSharedMemorySize, SNN_SMEM);
    cudaFuncSetAttribute(readout_kernel,
                         cudaFuncAttributeMaxDynamicSharedMemorySize, RDO_SMEM);

    transpose_kernel<<<(HDIM * HDIM + 255) / 256, 256>>>(W_rec, W_out);

    dim3 ggrid(HDIM / GBN, (T_STEPS * BATCH) / GBM);  // (4, 500)
    gemm_iin_kernel<<<ggrid, 256>>>(x, W_in);

    snn_kernel<<<NG * NS, 512, SNN_SMEM>>>();

    readout_kernel<<<BATCH, 512, RDO_SMEM>>>(b_out, out);
}